// round 11
// baseline (speedup 1.0000x reference)
#include <cuda_runtime.h>
#include <math.h>
#include <stdint.h>

// KMeans assignment via mma.sync TF32 split-2 (AhBh + AhBl + AlBh, fp32 accum).
// out[i] = argmin_k ( cnorm[k] - 2 * dot(X[i,:], C[:,k]) ), index as float32.
// N=131072, D=768, K=2048 fp32. Target: base sm_100 (tcgen05 unavailable).
//
// R10->R11: single-buffer BK=16, 32KB STATIC smem (no cudaFuncSetAttribute,
// no dynamic smem — removes the only construct every passing kernel lacked).
// 2 CTAs/SM replace double-buffering for phase overlap. 128x128 block tile,
// 2x4 warps, warp tile 64x32, fragment-packed smem (LDS.128/LDS.64 frag loads).

#define N_ROWS 131072
#define D_DIM  768
#define K_CENT 2048
#define BM 128
#define BN 128
#define BK 16
#define NTHREADS 256
#define NCHUNK (K_CENT / BN)   // 16
#define NSLAB  (D_DIM / BK)    // 48

static __device__ __forceinline__ float tf32r(float v) {
    uint32_t r; asm("cvt.rna.tf32.f32 %0, %1;" : "=r"(r) : "f"(v));
    return __uint_as_float(r);
}
static __device__ __forceinline__ void mma8(float* d, const uint32_t* a, const uint32_t* b) {
    asm volatile(
        "mma.sync.aligned.m16n8k8.row.col.f32.tf32.tf32.f32 "
        "{%0,%1,%2,%3}, {%4,%5,%6,%7}, {%8,%9}, {%0,%1,%2,%3};"
        : "+f"(d[0]), "+f"(d[1]), "+f"(d[2]), "+f"(d[3])
        : "r"(a[0]), "r"(a[1]), "r"(a[2]), "r"(a[3]), "r"(b[0]), "r"(b[1]));
}

__global__ void __launch_bounds__(NTHREADS, 2)
kmeans_mma_kernel(const float* __restrict__ X, const float* __restrict__ C,
                  const float* __restrict__ cnorm, float* __restrict__ out)
{
    // Fragment-packed tiles, single-buffered:
    //  As: [hl][mt(8)][ks(2)][128]  = 4096 floats (16 KB)
    //  Bs: [hl][nt(16)][ks(2)][64]  = 4096 floats (16 KB)
    __shared__ float As[4096];
    __shared__ float Bs[4096];

    const int tid  = threadIdx.x;
    const int lane = tid & 31;
    const int warp = tid >> 5;
    const int wm   = warp >> 2;          // 0..1 (m half)
    const int wn   = warp & 3;           // 0..3 (n quarter)
    const int g    = lane >> 2;          // groupID (row within frag)
    const int tig  = lane & 3;           // thread-in-group (col pair)
    const int brow = blockIdx.x * BM;

    float bestv[8];
    int   besti[8];
#pragma unroll
    for (int i = 0; i < 8; i++) { bestv[i] = INFINITY; besti[i] = 0; }

    for (int kc = 0; kc < NCHUNK; kc++) {
        const int k0 = kc * BN;
        float acc[4][4][4];
#pragma unroll
        for (int i = 0; i < 4; i++)
#pragma unroll
            for (int j = 0; j < 4; j++)
#pragma unroll
                for (int c = 0; c < 4; c++) acc[i][j][c] = 0.0f;

        // ---- prologue LDG: slab 0 ----
        float4 ar[2], cr[2];
#pragma unroll
        for (int l = 0; l < 2; l++) {
            int f = tid + l * NTHREADS;
            ar[l] = *(const float4*)&X[(size_t)(brow + (f >> 2)) * D_DIM + (f & 3) * 4];
            cr[l] = *(const float4*)&C[(size_t)(f >> 5) * K_CENT + k0 + (f & 31) * 4];
        }

        for (int s = 0; s < NSLAB; s++) {
            // ---- store X slab (fragment-packed, hi+lo planes) ----
#pragma unroll
            for (int l = 0; l < 2; l++) {
                int f = tid + l * NTHREADS;
                int xrow = f >> 2, xk4 = (f & 3) * 4;
                int mt = xrow >> 4, rr = xrow & 15;
                int gg = rr & 7, hb = rr >> 3;
                float v4[4] = {ar[l].x, ar[l].y, ar[l].z, ar[l].w};
#pragma unroll
                for (int c = 0; c < 4; c++) {
                    int k = xk4 + c, ks = k >> 3, kk = k & 7;
                    int pos = (gg * 4 + (kk & 3)) * 4 + (((kk >> 2) << 1) | hb);
                    int base = (mt * 2 + ks) * 128 + pos;
                    float hi = tf32r(v4[c]);
                    As[base]        = hi;
                    As[base + 2048] = v4[c] - hi;   // lo plane
                }
            }
            // ---- store C slab (fragment-packed, hi+lo planes) ----
#pragma unroll
            for (int l = 0; l < 2; l++) {
                int f = tid + l * NTHREADS;
                int cd = f >> 5, cn4 = (f & 31) * 4;
                int ks = cd >> 3, kk = cd & 7;
                float v4[4] = {cr[l].x, cr[l].y, cr[l].z, cr[l].w};
#pragma unroll
                for (int c = 0; c < 4; c++) {
                    int n = cn4 + c, nt = n >> 3, nn = n & 7;
                    int pos = (nn * 4 + (kk & 3)) * 2 + (kk >> 2);
                    int base = (nt * 2 + ks) * 64 + pos;
                    float hi = tf32r(v4[c]);
                    Bs[base]        = hi;
                    Bs[base + 2048] = v4[c] - hi;   // lo plane
                }
            }

            // ---- prefetch next slab (LDG latency hides under sync+MMA) ----
            if (s + 1 < NSLAB) {
                const int d0 = (s + 1) * BK;
#pragma unroll
                for (int l = 0; l < 2; l++) {
                    int f = tid + l * NTHREADS;
                    ar[l] = *(const float4*)&X[(size_t)(brow + (f >> 2)) * D_DIM + d0 + (f & 3) * 4];
                    cr[l] = *(const float4*)&C[(size_t)(d0 + (f >> 5)) * K_CENT + k0 + (f & 31) * 4];
                }
            }
            __syncthreads();

            // ---- compute: 2 k8 steps x (16 tiles x 3 products) ----
#pragma unroll
            for (int ks = 0; ks < 2; ks++) {
                uint4 ah[4], al[4]; uint2 bh[4], bl[4];
#pragma unroll
                for (int i = 0; i < 4; i++) {
                    int mt = wm * 4 + i;
                    ah[i] = *(const uint4*)&As[(mt * 2 + ks) * 128 + lane * 4];
                    al[i] = *(const uint4*)&As[(mt * 2 + ks) * 128 + lane * 4 + 2048];
                }
#pragma unroll
                for (int j = 0; j < 4; j++) {
                    int nt = wn * 4 + j;
                    bh[j] = *(const uint2*)&Bs[(nt * 2 + ks) * 64 + lane * 2];
                    bl[j] = *(const uint2*)&Bs[(nt * 2 + ks) * 64 + lane * 2 + 2048];
                }
#pragma unroll
                for (int i = 0; i < 4; i++)
#pragma unroll
                    for (int j = 0; j < 4; j++) {
                        mma8(acc[i][j], (const uint32_t*)&ah[i], (const uint32_t*)&bh[j]);
                        mma8(acc[i][j], (const uint32_t*)&ah[i], (const uint32_t*)&bl[j]);
                        mma8(acc[i][j], (const uint32_t*)&al[i], (const uint32_t*)&bh[j]);
                    }
            }
            __syncthreads();   // compute done before next store overwrites
        }

        // ---- fold chunk into running argmin ----
        // acc[i][j]: c0:(row g, col) c1:(g, col+1) c2:(g+8, col) c3:(g+8, col+1)
#pragma unroll
        for (int i = 0; i < 4; i++)
#pragma unroll
            for (int h = 0; h < 2; h++) {
                int slot = i * 2 + h;
#pragma unroll
                for (int j = 0; j < 4; j++)
#pragma unroll
                    for (int c = 0; c < 2; c++) {
                        int k = k0 + wn * 32 + j * 8 + tig * 2 + c;
                        float sv = fmaf(-2.0f, acc[i][j][h * 2 + c], __ldg(&cnorm[k]));
                        if (sv < bestv[slot] || (sv == bestv[slot] && k < besti[slot])) {
                            bestv[slot] = sv; besti[slot] = k;
                        }
                    }
            }
    }

    // ---- reduce over tig (4 lanes share each row) ----
#pragma unroll
    for (int slot = 0; slot < 8; slot++) {
        float v = bestv[slot]; int bi = besti[slot];
#pragma unroll
        for (int off = 2; off > 0; off >>= 1) {
            float ov = __shfl_down_sync(0xffffffffu, v,  off, 4);
            int   oi = __shfl_down_sync(0xffffffffu, bi, off, 4);
            if (ov < v || (ov == v && oi < bi)) { v = ov; bi = oi; }
        }
        bestv[slot] = v; besti[slot] = bi;
    }

    // ---- cross-warp (wn) reduce via smem (tiles are dead now) ----
    __syncthreads();
    float* sv_arr = As;              // [4][128]
    int*   si_arr = (int*)Bs;        // [4][128]
    if (tig == 0) {
#pragma unroll
        for (int i = 0; i < 4; i++)
#pragma unroll
            for (int h = 0; h < 2; h++) {
                int row = wm * 64 + i * 16 + h * 8 + g;
                sv_arr[wn * 128 + row] = bestv[i * 2 + h];
                si_arr[wn * 128 + row] = besti[i * 2 + h];
            }
    }
    __syncthreads();
    if (tid < BM) {
        float v = sv_arr[tid]; int bi = si_arr[tid];
#pragma unroll
        for (int w = 1; w < 4; w++) {
            float ov = sv_arr[w * 128 + tid];
            int   oi = si_arr[w * 128 + tid];
            if (ov < v || (ov == v && oi < bi)) { v = ov; bi = oi; }
        }
        out[brow + tid] = (float)bi;
    }
}

extern "C" void kernel_launch(void* const* d_in, const int* in_sizes, int n_in,
                              void* d_out, int out_size)
{
    const float* X = nullptr;
    const float* C = nullptr;
    const float* cnorm = nullptr;
    for (int i = 0; i < n_in; i++) {
        if      (in_sizes[i] == N_ROWS * D_DIM) X     = (const float*)d_in[i];
        else if (in_sizes[i] == D_DIM * K_CENT) C     = (const float*)d_in[i];
        else if (in_sizes[i] == K_CENT)         cnorm = (const float*)d_in[i];
    }
    float* out = (float*)d_out;

    kmeans_mma_kernel<<<N_ROWS / BM, NTHREADS>>>(X, C, cnorm, out);
}

// round 14
// speedup vs baseline: 2.2267x; 2.2267x over previous
#include <cuda_runtime.h>
#include <math.h>
#include <stdint.h>

// KMeans assignment via mma.sync TF32 split-2 (AhBh + AhBl + AlBh, fp32 accum).
// out[i] = argmin_k ( cnorm[k] - 2 * dot(X[i,:], C[:,k]) ), index as float32.
// N=131072, D=768, K=2048 fp32. Target: base sm_100.
//
// R14 = R11's PASSING skeleton (single buffer, launch_bounds(256,2), hi/lo
// split at store, 2 syncs/slab) with exactly one change: the B tile layout.
// R11's fragment-packed B had 16-way STS bank conflicts (L1=89%, tensor=22%).
// Now B is hi/lo planes in padded row-major [hl][k][132]: stores are
// conflict-free STS.128, fragment loads are <=2-way scalar LDS.

#define N_ROWS 131072
#define D_DIM  768
#define K_CENT 2048
#define BM 128
#define BN 128
#define BK 16
#define NTHREADS 256
#define NCHUNK (K_CENT / BN)   // 16
#define NSLAB  (D_DIM / BK)    // 48
#define BSTRIDE 132            // 128 + 4 pad

static __device__ __forceinline__ float tf32r(float v) {
    uint32_t r; asm("cvt.rna.tf32.f32 %0, %1;" : "=r"(r) : "f"(v));
    return __uint_as_float(r);
}
static __device__ __forceinline__ void mma8(float* d, const uint32_t* a, const uint32_t* b) {
    asm volatile(
        "mma.sync.aligned.m16n8k8.row.col.f32.tf32.tf32.f32 "
        "{%0,%1,%2,%3}, {%4,%5,%6,%7}, {%8,%9}, {%0,%1,%2,%3};"
        : "+f"(d[0]), "+f"(d[1]), "+f"(d[2]), "+f"(d[3])
        : "r"(a[0]), "r"(a[1]), "r"(a[2]), "r"(a[3]), "r"(b[0]), "r"(b[1]));
}

__global__ void __launch_bounds__(NTHREADS, 2)
kmeans_mma_kernel(const float* __restrict__ X, const float* __restrict__ C,
                  const float* __restrict__ cnorm, float* __restrict__ out)
{
    // A: fragment-packed hi/lo planes [hl][mt(8)][ks(2)][128] -> 16 KB
    // B: row-major padded hi/lo planes [hl][k(16)][132]       -> 16.9 KB
    __shared__ float As[2][8][2][128];
    __shared__ float Bs[2][BK][BSTRIDE];

    const int tid  = threadIdx.x;
    const int lane = tid & 31;
    const int warp = tid >> 5;
    const int wm   = warp >> 2;          // 0..1 (m half)
    const int wn   = warp & 3;           // 0..3 (n quarter)
    const int g    = lane >> 2;          // groupID
    const int tig  = lane & 3;           // thread-in-group
    const int brow = blockIdx.x * BM;

    float bestv[8];
    int   besti[8];
#pragma unroll
    for (int i = 0; i < 8; i++) { bestv[i] = INFINITY; besti[i] = 0; }

    for (int kc = 0; kc < NCHUNK; kc++) {
        const int k0 = kc * BN;
        float acc[4][4][4];
#pragma unroll
        for (int i = 0; i < 4; i++)
#pragma unroll
            for (int j = 0; j < 4; j++)
#pragma unroll
                for (int c = 0; c < 4; c++) acc[i][j][c] = 0.0f;

        // ---- prologue LDG: slab 0 ----
        float4 ar[2], cr[2];
#pragma unroll
        for (int l = 0; l < 2; l++) {
            int f = tid + l * NTHREADS;
            ar[l] = *(const float4*)&X[(size_t)(brow + (f >> 2)) * D_DIM + (f & 3) * 4];
            cr[l] = *(const float4*)&C[(size_t)(f >> 5) * K_CENT + k0 + (f & 31) * 4];
        }

        for (int s = 0; s < NSLAB; s++) {
            // ---- store X slab (fragment-packed, hi+lo planes; as in R11) ----
#pragma unroll
            for (int l = 0; l < 2; l++) {
                int f = tid + l * NTHREADS;
                int xrow = f >> 2, xk4 = (f & 3) * 4;
                int mt = xrow >> 4, rr = xrow & 15;
                int gg = rr & 7, hb = rr >> 3;
                float v4[4] = {ar[l].x, ar[l].y, ar[l].z, ar[l].w};
#pragma unroll
                for (int c = 0; c < 4; c++) {
                    int k = xk4 + c, ks = k >> 3, kk = k & 7;
                    int pos = (gg * 4 + (kk & 3)) * 4 + (((kk >> 2) << 1) | hb);
                    float hi = tf32r(v4[c]);
                    As[0][mt][ks][pos] = hi;
                    As[1][mt][ks][pos] = v4[c] - hi;
                }
            }
            // ---- store C slab (hi/lo planes, row-major padded, STS.128) ----
#pragma unroll
            for (int l = 0; l < 2; l++) {
                int f = tid + l * NTHREADS;
                int row = f >> 5, col = (f & 31) * 4;
                float hx = tf32r(cr[l].x), hy = tf32r(cr[l].y),
                      hz = tf32r(cr[l].z), hw = tf32r(cr[l].w);
                float4 hi4 = make_float4(hx, hy, hz, hw);
                float4 lo4 = make_float4(cr[l].x - hx, cr[l].y - hy,
                                         cr[l].z - hz, cr[l].w - hw);
                *(float4*)&Bs[0][row][col] = hi4;
                *(float4*)&Bs[1][row][col] = lo4;
            }

            // ---- prefetch next slab (latency hides under sync+MMA) ----
            if (s + 1 < NSLAB) {
                const int d0 = (s + 1) * BK;
#pragma unroll
                for (int l = 0; l < 2; l++) {
                    int f = tid + l * NTHREADS;
                    ar[l] = *(const float4*)&X[(size_t)(brow + (f >> 2)) * D_DIM + d0 + (f & 3) * 4];
                    cr[l] = *(const float4*)&C[(size_t)(d0 + (f >> 5)) * K_CENT + k0 + (f & 31) * 4];
                }
            }
            __syncthreads();

            // ---- compute: 2 k8 steps x 16 tiles x 3 products ----
#pragma unroll
            for (int ks = 0; ks < 2; ks++) {
                uint4 ah[4], al[4];
                uint32_t bh[4][2], bl[4][2];
#pragma unroll
                for (int i = 0; i < 4; i++) {
                    int mt = wm * 4 + i;
                    ah[i] = *(const uint4*)&As[0][mt][ks][lane * 4];
                    al[i] = *(const uint4*)&As[1][mt][ks][lane * 4];
                }
#pragma unroll
                for (int j = 0; j < 4; j++) {
                    int ncol = (wn * 4 + j) * 8 + g;
                    bh[j][0] = __float_as_uint(Bs[0][ks * 8 + tig][ncol]);
                    bh[j][1] = __float_as_uint(Bs[0][ks * 8 + tig + 4][ncol]);
                    bl[j][0] = __float_as_uint(Bs[1][ks * 8 + tig][ncol]);
                    bl[j][1] = __float_as_uint(Bs[1][ks * 8 + tig + 4][ncol]);
                }
#pragma unroll
                for (int i = 0; i < 4; i++)
#pragma unroll
                    for (int j = 0; j < 4; j++) {
                        mma8(acc[i][j], (const uint32_t*)&ah[i], bh[j]);
                        mma8(acc[i][j], (const uint32_t*)&ah[i], bl[j]);
                        mma8(acc[i][j], (const uint32_t*)&al[i], bh[j]);
                    }
            }
            __syncthreads();   // compute done before next store overwrites
        }

        // ---- fold chunk into running argmin ----
        // acc[i][j]: c0:(row g, col) c1:(g, col+1) c2:(g+8, col) c3:(g+8, col+1)
#pragma unroll
        for (int i = 0; i < 4; i++)
#pragma unroll
            for (int h = 0; h < 2; h++) {
                int slot = i * 2 + h;
#pragma unroll
                for (int j = 0; j < 4; j++)
#pragma unroll
                    for (int c = 0; c < 2; c++) {
                        int k = k0 + wn * 32 + j * 8 + tig * 2 + c;
                        float sv = fmaf(-2.0f, acc[i][j][h * 2 + c], __ldg(&cnorm[k]));
                        if (sv < bestv[slot] || (sv == bestv[slot] && k < besti[slot])) {
                            bestv[slot] = sv; besti[slot] = k;
                        }
                    }
            }
    }

    // ---- reduce over tig (4 lanes share each row) ----
#pragma unroll
    for (int slot = 0; slot < 8; slot++) {
        float v = bestv[slot]; int bi = besti[slot];
#pragma unroll
        for (int off = 2; off > 0; off >>= 1) {
            float ov = __shfl_down_sync(0xffffffffu, v,  off, 4);
            int   oi = __shfl_down_sync(0xffffffffu, bi, off, 4);
            if (ov < v || (ov == v && oi < bi)) { v = ov; bi = oi; }
        }
        bestv[slot] = v; besti[slot] = bi;
    }

    // ---- cross-warp (wn) reduce via smem (tiles dead) ----
    __syncthreads();
    float* sv_arr = &As[0][0][0][0];     // [4][128]
    int*   si_arr = (int*)&Bs[0][0][0];  // [4][128]
    if (tig == 0) {
#pragma unroll
        for (int i = 0; i < 4; i++)
#pragma unroll
            for (int h = 0; h < 2; h++) {
                int row = wm * 64 + i * 16 + h * 8 + g;
                sv_arr[wn * 128 + row] = bestv[i * 2 + h];
                si_arr[wn * 128 + row] = besti[i * 2 + h];
            }
    }
    __syncthreads();
    if (tid < BM) {
        float v = sv_arr[tid]; int bi = si_arr[tid];
#pragma unroll
        for (int w = 1; w < 4; w++) {
            float ov = sv_arr[w * 128 + tid];
            int   oi = si_arr[w * 128 + tid];
            if (ov < v || (ov == v && oi < bi)) { v = ov; bi = oi; }
        }
        out[brow + tid] = (float)bi;
    }
}

extern "C" void kernel_launch(void* const* d_in, const int* in_sizes, int n_in,
                              void* d_out, int out_size)
{
    const float* X = nullptr;
    const float* C = nullptr;
    const float* cnorm = nullptr;
    for (int i = 0; i < n_in; i++) {
        if      (in_sizes[i] == N_ROWS * D_DIM) X     = (const float*)d_in[i];
        else if (in_sizes[i] == D_DIM * K_CENT) C     = (const float*)d_in[i];
        else if (in_sizes[i] == K_CENT)         cnorm = (const float*)d_in[i];
    }
    float* out = (float*)d_out;

    kmeans_mma_kernel<<<N_ROWS / BM, NTHREADS>>>(X, C, cnorm, out);
}

// round 15
// speedup vs baseline: 5.5858x; 2.5086x over previous
#include <cuda_runtime.h>
#include <cuda_fp16.h>
#include <math.h>
#include <stdint.h>

// KMeans assignment via mma.sync fp16 split-2 (AhBh + AhBl + AlBh, fp32 accum).
// out[i] = argmin_k ( cnorm[k] - 2 * dot(X[i,:], C[:,k]) ), index as float32.
// N=131072, D=768, K=2048 fp32. Target: base sm_100.
//
// R15: fp16 m16n8k16 + ldmatrix (vs R14 tf32 m16n8k8 + scalar LDS):
//  - half the MMA instructions at 2x HMMA rate -> tensor floor ~2.2ms
//  - fp16 smem + swizzled row-major + ldmatrix -> ~1/3 the L1 wavefronts
// Precision: hi=fp16(x), lo=fp16(x-hi); dropped AlBl term ~2^-22 rel,
// better than the tf32 split that measured rel_err = 0.0.
// Skeleton = R14 (single buffer, launch_bounds(256,2), 2 syncs/slab).

#define N_ROWS 131072
#define D_DIM  768
#define K_CENT 2048
#define BM 128
#define BN 128
#define BK 16
#define NTHREADS 256
#define NCHUNK (K_CENT / BN)   // 16
#define NSLAB  (D_DIM / BK)    // 48

static __device__ __forceinline__ void mma16(float* d, const uint32_t* a, const uint32_t* b) {
    asm volatile(
        "mma.sync.aligned.m16n8k16.row.col.f32.f16.f16.f32 "
        "{%0,%1,%2,%3}, {%4,%5,%6,%7}, {%8,%9}, {%0,%1,%2,%3};"
        : "+f"(d[0]), "+f"(d[1]), "+f"(d[2]), "+f"(d[3])
        : "r"(a[0]), "r"(a[1]), "r"(a[2]), "r"(a[3]), "r"(b[0]), "r"(b[1]));
}
static __device__ __forceinline__ void ldm_x4(uint32_t* r, uint32_t saddr) {
    asm volatile("ldmatrix.sync.aligned.m8n8.x4.shared.b16 {%0,%1,%2,%3}, [%4];"
        : "=r"(r[0]), "=r"(r[1]), "=r"(r[2]), "=r"(r[3]) : "r"(saddr));
}
static __device__ __forceinline__ void ldm_x4_t(uint32_t* r, uint32_t saddr) {
    asm volatile("ldmatrix.sync.aligned.m8n8.x4.trans.shared.b16 {%0,%1,%2,%3}, [%4];"
        : "=r"(r[0]), "=r"(r[1]), "=r"(r[2]), "=r"(r[3]) : "r"(saddr));
}
static __device__ __forceinline__ uint32_t s2u(const void* p) {
    uint32_t a;
    asm("{ .reg .u64 t; cvta.to.shared.u64 t, %1; cvt.u32.u64 %0, t; }"
        : "=r"(a) : "l"(p));
    return a;
}

__global__ void __launch_bounds__(NTHREADS, 2)
kmeans_mma_kernel(const float* __restrict__ X, const float* __restrict__ C,
                  const float* __restrict__ cnorm, float* __restrict__ out)
{
    // A: fp16, per plane 8 mt-tiles x (16 rows x 16 k) = 512B/mt, swizzled
    //    chunk ci = (2r + c) ^ ((r>>2)&1)    (r = row in tile, c = k>>3)
    // B: fp16, per plane 16 k-rows x 128 n = 256B/row, swizzled
    //    chunk = (n>>3) ^ (k&7)
    __shared__ __align__(16) uint8_t Asm[2][4096];   // hi, lo planes (8 KB)
    __shared__ __align__(16) uint8_t Bsm[2][4096];   // hi, lo planes (8 KB)

    const int tid  = threadIdx.x;
    const int lane = tid & 31;
    const int warp = tid >> 5;
    const int wm   = warp >> 2;          // 0..1 (m half)
    const int wn   = warp & 3;           // 0..3 (n quarter)
    const int g    = lane >> 2;          // groupID
    const int tig  = lane & 3;           // thread-in-group
    const int brow = blockIdx.x * BM;

    const uint32_t Abase = s2u(Asm);
    const uint32_t Bbase = s2u(Bsm);

    // Per-lane ldmatrix address components (constant across slabs):
    // pieces p = lane>>3: A: row (p&1)*8+(lane&7) in tile, c = p>>1
    //                     B: k  (p&1)*8+(lane&7),          cn += p>>1
    const int pA  = lane >> 3;
    const int rA  = ((pA & 1) << 3) | (lane & 7);
    const int cA  = pA >> 1;
    const uint32_t a_ci_off = (uint32_t)(((2 * rA + cA) ^ ((rA >> 2) & 1)) << 4);
    const uint32_t b_row_off = (uint32_t)(rA << 8);   // kB * 256
    const int k7    = lane & 7;
    const int cnadd = pA >> 1;

    // LDG coordinates
    const int x_r0 = tid >> 2, x_kb = (tid & 3) * 4;              // + l*64 rows
    const int c_kp = tid >> 5, c_n4 = (tid & 31) * 4;             // rows 2kp,2kp+1

    float bestv[8];
    int   besti[8];
#pragma unroll
    for (int i = 0; i < 8; i++) { bestv[i] = INFINITY; besti[i] = 0; }

    for (int kc = 0; kc < NCHUNK; kc++) {
        const int k0 = kc * BN;
        float acc[4][4][4];
#pragma unroll
        for (int i = 0; i < 4; i++)
#pragma unroll
            for (int j = 0; j < 4; j++)
#pragma unroll
                for (int c = 0; c < 4; c++) acc[i][j][c] = 0.0f;

        // ---- prologue LDG: slab 0 ----
        float4 ar[2], cr[2];
#pragma unroll
        for (int l = 0; l < 2; l++)
            ar[l] = *(const float4*)&X[(size_t)(brow + x_r0 + l * 64) * D_DIM + x_kb];
        cr[0] = *(const float4*)&C[(size_t)(2 * c_kp)     * K_CENT + k0 + c_n4];
        cr[1] = *(const float4*)&C[(size_t)(2 * c_kp + 1) * K_CENT + k0 + c_n4];

        for (int s = 0; s < NSLAB; s++) {
            // ---- store X slab: hi/lo fp16 planes, swizzled, STS.64 ----
#pragma unroll
            for (int l = 0; l < 2; l++) {
                int rg = x_r0 + l * 64;
                int mt = rg >> 4, r = rg & 15;
                int ci = (2 * r + (x_kb >> 3)) ^ ((r >> 2) & 1);
                uint32_t boff = (uint32_t)(mt * 512 + ci * 16 + ((x_kb & 4) << 1));
                float4 v = ar[l];
                __half2 h01 = __floats2half2_rn(v.x, v.y);
                __half2 h23 = __floats2half2_rn(v.z, v.w);
                float2 f01 = __half22float2(h01);
                float2 f23 = __half22float2(h23);
                __half2 l01 = __floats2half2_rn(v.x - f01.x, v.y - f01.y);
                __half2 l23 = __floats2half2_rn(v.z - f23.x, v.w - f23.y);
                uint2 hw; hw.x = *(uint32_t*)&h01; hw.y = *(uint32_t*)&h23;
                uint2 lw; lw.x = *(uint32_t*)&l01; lw.y = *(uint32_t*)&l23;
                *(uint2*)(&Asm[0][boff]) = hw;
                *(uint2*)(&Asm[1][boff]) = lw;
            }
            // ---- store C slab: hi/lo fp16 planes, swizzled, STS.64 ----
            {
                int r0 = 2 * c_kp, r1 = r0 + 1;
                int cn = c_n4 >> 3; uint32_t inoff = (uint32_t)((c_n4 & 4) << 1);
                uint32_t b0off = (uint32_t)(r0 * 256 + ((cn ^ (r0 & 7)) << 4)) + inoff;
                uint32_t b1off = (uint32_t)(r1 * 256 + ((cn ^ (r1 & 7)) << 4)) + inoff;
                float4 v0 = cr[0], v1 = cr[1];
                __half2 h0a = __floats2half2_rn(v0.x, v0.y);
                __half2 h0b = __floats2half2_rn(v0.z, v0.w);
                __half2 h1a = __floats2half2_rn(v1.x, v1.y);
                __half2 h1b = __floats2half2_rn(v1.z, v1.w);
                float2 g0a = __half22float2(h0a), g0b = __half22float2(h0b);
                float2 g1a = __half22float2(h1a), g1b = __half22float2(h1b);
                __half2 l0a = __floats2half2_rn(v0.x - g0a.x, v0.y - g0a.y);
                __half2 l0b = __floats2half2_rn(v0.z - g0b.x, v0.w - g0b.y);
                __half2 l1a = __floats2half2_rn(v1.x - g1a.x, v1.y - g1a.y);
                __half2 l1b = __floats2half2_rn(v1.z - g1b.x, v1.w - g1b.y);
                uint2 w;
                w.x = *(uint32_t*)&h0a; w.y = *(uint32_t*)&h0b; *(uint2*)(&Bsm[0][b0off]) = w;
                w.x = *(uint32_t*)&l0a; w.y = *(uint32_t*)&l0b; *(uint2*)(&Bsm[1][b0off]) = w;
                w.x = *(uint32_t*)&h1a; w.y = *(uint32_t*)&h1b; *(uint2*)(&Bsm[0][b1off]) = w;
                w.x = *(uint32_t*)&l1a; w.y = *(uint32_t*)&l1b; *(uint2*)(&Bsm[1][b1off]) = w;
            }

            // ---- prefetch next slab into registers ----
            if (s + 1 < NSLAB) {
                const int d0 = (s + 1) * BK;
#pragma unroll
                for (int l = 0; l < 2; l++)
                    ar[l] = *(const float4*)&X[(size_t)(brow + x_r0 + l * 64) * D_DIM + d0 + x_kb];
                cr[0] = *(const float4*)&C[(size_t)(d0 + 2 * c_kp)     * K_CENT + k0 + c_n4];
                cr[1] = *(const float4*)&C[(size_t)(d0 + 2 * c_kp + 1) * K_CENT + k0 + c_n4];
            }
            __syncthreads();

            // ---- compute: one K=16 step, 16 tiles x 3 products ----
            uint32_t ah[4][4], al[4][4], bh[2][4], bl[2][4];
#pragma unroll
            for (int i = 0; i < 4; i++) {
                uint32_t aoff = (uint32_t)((wm * 4 + i) * 512) + a_ci_off;
                ldm_x4(ah[i], Abase + aoff);
                ldm_x4(al[i], Abase + 4096u + aoff);
            }
#pragma unroll
            for (int jj = 0; jj < 2; jj++) {
                int cn = wn * 4 + jj * 2 + cnadd;
                uint32_t boff = b_row_off + (uint32_t)((cn ^ k7) << 4);
                ldm_x4_t(bh[jj], Bbase + boff);
                ldm_x4_t(bl[jj], Bbase + 4096u + boff);
            }
#pragma unroll
            for (int i = 0; i < 4; i++)
#pragma unroll
                for (int j = 0; j < 4; j++) {
                    const uint32_t* bhp = &bh[j >> 1][(j & 1) * 2];
                    const uint32_t* blp = &bl[j >> 1][(j & 1) * 2];
                    mma16(acc[i][j], ah[i], bhp);
                    mma16(acc[i][j], ah[i], blp);
                    mma16(acc[i][j], al[i], bhp);
                }
            __syncthreads();   // compute done before next store overwrites
        }

        // ---- fold chunk into running argmin ----
        // acc[i][j]: c0:(row g, col) c1:(g, col+1) c2:(g+8, col) c3:(g+8, col+1)
#pragma unroll
        for (int i = 0; i < 4; i++)
#pragma unroll
            for (int h = 0; h < 2; h++) {
                int slot = i * 2 + h;
#pragma unroll
                for (int j = 0; j < 4; j++)
#pragma unroll
                    for (int c = 0; c < 2; c++) {
                        int k = k0 + wn * 32 + j * 8 + tig * 2 + c;
                        float sv = fmaf(-2.0f, acc[i][j][h * 2 + c], __ldg(&cnorm[k]));
                        if (sv < bestv[slot] || (sv == bestv[slot] && k < besti[slot])) {
                            bestv[slot] = sv; besti[slot] = k;
                        }
                    }
            }
    }

    // ---- reduce over tig (4 lanes share each row) ----
#pragma unroll
    for (int slot = 0; slot < 8; slot++) {
        float v = bestv[slot]; int bi = besti[slot];
#pragma unroll
        for (int off = 2; off > 0; off >>= 1) {
            float ov = __shfl_down_sync(0xffffffffu, v,  off, 4);
            int   oi = __shfl_down_sync(0xffffffffu, bi, off, 4);
            if (ov < v || (ov == v && oi < bi)) { v = ov; bi = oi; }
        }
        bestv[slot] = v; besti[slot] = bi;
    }

    // ---- cross-warp (wn) reduce via smem (tiles dead) ----
    __syncthreads();
    float* sv_arr = (float*)&Asm[0][0];   // [4][128] floats (2 KB)
    int*   si_arr = (int*)&Bsm[0][0];     // [4][128] ints  (2 KB)
    if (tig == 0) {
#pragma unroll
        for (int i = 0; i < 4; i++)
#pragma unroll
            for (int h = 0; h < 2; h++) {
                int row = wm * 64 + i * 16 + h * 8 + g;
                sv_arr[wn * 128 + row] = bestv[i * 2 + h];
                si_arr[wn * 128 + row] = besti[i * 2 + h];
            }
    }
    __syncthreads();
    if (tid < BM) {
        float v = sv_arr[tid]; int bi = si_arr[tid];
#pragma unroll
        for (int w = 1; w < 4; w++) {
            float ov = sv_arr[w * 128 + tid];
            int   oi = si_arr[w * 128 + tid];
            if (ov < v || (ov == v && oi < bi)) { v = ov; bi = oi; }
        }
        out[brow + tid] = (float)bi;
    }
}

extern "C" void kernel_launch(void* const* d_in, const int* in_sizes, int n_in,
                              void* d_out, int out_size)
{
    const float* X = nullptr;
    const float* C = nullptr;
    const float* cnorm = nullptr;
    for (int i = 0; i < n_in; i++) {
        if      (in_sizes[i] == N_ROWS * D_DIM) X     = (const float*)d_in[i];
        else if (in_sizes[i] == D_DIM * K_CENT) C     = (const float*)d_in[i];
        else if (in_sizes[i] == K_CENT)         cnorm = (const float*)d_in[i];
    }
    float* out = (float*)d_out;

    kmeans_mma_kernel<<<N_ROWS / BM, NTHREADS>>>(X, C, cnorm, out);
}